// round 1
// baseline (speedup 1.0000x reference)
#include <cuda_runtime.h>

// Problem constants
#define BATCH 1024
#define CCH   3
#define HH    224
#define WW    220
#define PROWS 4
#define PCOLS 5
#define NPATCH 20
#define HID   32
#define PH    56          // HH / PROWS
#define PW    44          // WW / PCOLS
#define V4_PER_ROW   11   // PW / 4
#define ROWS_PER_PATCH (CCH * PH)                 // 168
#define V4_PER_PATCH   (ROWS_PER_PATCH * V4_PER_ROW)  // 1848

// Scratch for contribs if the output buffer doesn't hold them
__device__ float g_contribs[BATCH * NPATCH];

__global__ __launch_bounds__(256) void patch_mlp_kernel(
    const float* __restrict__ x,
    const float* __restrict__ w1,
    const float* __restrict__ b1,
    const float* __restrict__ w2,
    const float* __restrict__ b2,
    float* __restrict__ contribs)
{
    const int blk = blockIdx.x;          // b * NPATCH + p
    const int b = blk / NPATCH;
    const int p = blk - b * NPATCH;
    const int pr = p / PCOLS;            // patch row
    const int pc = p - pr * PCOLS;       // patch col
    const int tid = threadIdx.x;

    const long long xbase = (long long)b * (CCH * HH * WW)
                          + (long long)(pr * PH) * WW
                          + pc * PW;

    float sum = 0.0f;
    // 1848 float4 per patch, strided across 256 threads (~7.2 each)
    for (int i = tid; i < V4_PER_PATCH; i += 256) {
        int ch  = i / (PH * V4_PER_ROW);
        int rem = i - ch * (PH * V4_PER_ROW);
        int hl  = rem / V4_PER_ROW;
        int v   = rem - hl * V4_PER_ROW;
        long long off = xbase + (long long)ch * (HH * WW) + (long long)hl * WW + v * 4;
        float4 d = *reinterpret_cast<const float4*>(x + off);
        sum += (d.x + d.y) + (d.z + d.w);
    }

    // warp reduce
    #pragma unroll
    for (int o = 16; o > 0; o >>= 1)
        sum += __shfl_down_sync(0xffffffffu, sum, o);

    __shared__ float ws[8];
    if ((tid & 31) == 0) ws[tid >> 5] = sum;
    __syncthreads();

    if (tid == 0) {
        float s = 0.0f;
        #pragma unroll
        for (int w = 0; w < 8; w++) s += ws[w];
        const float f = s * (1.0f / (float)(CCH * PH * PW));  // patch mean

        // scalar MLP: relu(f*w1 + b1) . w2 + b2
        float acc = b2[p];
        const float* w1p = w1 + p * HID;
        const float* b1p = b1 + p * HID;
        const float* w2p = w2 + p * HID;
        #pragma unroll
        for (int k = 0; k < HID; k++) {
            float h = fmaf(f, w1p[k], b1p[k]);
            h = fmaxf(h, 0.0f);
            acc = fmaf(h, w2p[k], acc);
        }
        contribs[b * NPATCH + p] = acc;
    }
}

__global__ __launch_bounds__(256) void score_kernel(
    const float* __restrict__ contribs,
    float* __restrict__ score)
{
    int b = blockIdx.x * 256 + threadIdx.x;
    if (b < BATCH) {
        float s = 0.0f;
        #pragma unroll
        for (int p = 0; p < NPATCH; p++)
            s += contribs[b * NPATCH + p];
        score[b] = s;
    }
}

extern "C" void kernel_launch(void* const* d_in, const int* in_sizes, int n_in,
                              void* d_out, int out_size)
{
    const float* x  = (const float*)d_in[0];
    const float* w1 = (const float*)d_in[1];
    const float* b1 = (const float*)d_in[2];
    const float* w2 = (const float*)d_in[3];
    const float* b2 = (const float*)d_in[4];

    float* out = (float*)d_out;
    float* score_ptr    = nullptr;
    float* contribs_ptr = nullptr;

    if (out_size == BATCH * (NPATCH + 1)) {
        // (score, contribs) concatenated: score first
        score_ptr    = out;
        contribs_ptr = out + BATCH;
    } else if (out_size == BATCH) {
        // only score requested; contribs go to scratch
        score_ptr = out;
        cudaGetSymbolAddress((void**)&contribs_ptr, g_contribs);
    } else if (out_size == BATCH * NPATCH) {
        // only contribs requested
        contribs_ptr = out;
    } else {
        // fallback: assume score-first layout
        score_ptr    = out;
        contribs_ptr = out + BATCH;
    }

    patch_mlp_kernel<<<BATCH * NPATCH, 256>>>(x, w1, b1, w2, b2, contribs_ptr);
    if (score_ptr != nullptr) {
        score_kernel<<<(BATCH + 255) / 256, 256>>>(contribs_ptr, score_ptr);
    }
}